// round 2
// baseline (speedup 1.0000x reference)
#include <cuda_runtime.h>

// Problem constants
#define BATCH 8
#define NN    32   // set size n
#define DD    32   // hidden dim D
#define OUT   32   // fc out dim

// ---------------- persistent device scratch (no allocations allowed) ----------------
__device__ float gA[BATCH][DD * NN];        // A[d][i] = h[b,i,d]
__device__ float gC0[BATCH][DD * 32];       // eq p=0
__device__ float gC1[BATCH][DD * 32];       // eq p=1 * S
__device__ float gC2[BATCH][DD * 32];       // eq p=2 * S
__device__ float gC3[BATCH][DD * 32];       // eq p=3 * S
__device__ float gC4[BATCH][DD * 32];       // eq p=4 * S^2
__device__ float gBi[BATCH][32 * NN];       // [o][i]: c6*S^2*A_i + c8*A_i^3 summed over d
__device__ float gBj[BATCH][32 * NN];       // [o][j]: c5*S^2*A_j + c9*A_j^3 summed over d
__device__ float gTk[BATCH][32 * NN];       // [o][k]: c10*A_k^3 summed over d
__device__ float gConst[BATCH][32];         // c7*S^3 + c11*Csum summed over d, + eq_bias
__device__ float gS2[BATCH][DD];            // S^2 per d
__device__ float gS3[BATCH][DD];            // S^3 per d
__device__ float gCs[BATCH][DD];            // sum of A^3 per d
__device__ float gPart[BATCH][NN][32];      // deterministic partial sums per (b, i, o)

// ---------------- precompute: MLP + per-batch folded coefficient tables ----------------
__global__ __launch_bounds__(256) void precompute_kernel(
    const float* __restrict__ x,  const float* __restrict__ W1, const float* __restrict__ b1,
    const float* __restrict__ W2, const float* __restrict__ b2,
    const float* __restrict__ eq, const float* __restrict__ eqb)
{
    const int b = blockIdx.x;
    const int t = threadIdx.x;

    __shared__ __align__(16) float h1[NN][DD];
    __shared__ __align__(16) float As[DD][NN];
    __shared__ __align__(16) float A3[DD][NN];
    __shared__ __align__(16) float SA[DD][NN];
    __shared__ __align__(16) float E0[DD][32];
    __shared__ __align__(16) float E1[DD][32];
    __shared__ float S[DD], S2[DD], S3[DD], Cs[DD];

    const float* xb = x + b * NN * 16;

    // h1 = relu(x @ W1 + b1)   [i][d]
    for (int c = t; c < NN * DD; c += 256) {
        int i = c >> 5, d = c & 31;
        float acc = b1[d];
        #pragma unroll
        for (int e = 0; e < 16; e++) acc = fmaf(xb[i * 16 + e], W1[e * 32 + d], acc);
        h1[i][d] = fmaxf(acc, 0.0f);
    }
    __syncthreads();

    // h2 = relu(h1 @ W2 + b2), stored TRANSPOSED: As[d][i]
    for (int c = t; c < NN * DD; c += 256) {
        int i = c >> 5, d = c & 31;
        float acc = b2[d];
        #pragma unroll
        for (int e = 0; e < 32; e++) acc = fmaf(h1[i][e], W2[e * 32 + d], acc);
        As[d][i] = fmaxf(acc, 0.0f);
    }
    __syncthreads();

    if (t < 32) {
        float s = 0.0f, cs = 0.0f;
        #pragma unroll
        for (int i = 0; i < 32; i++) { float a = As[t][i]; s += a; cs += a * a * a; }
        S[t] = s; S2[t] = s * s; S3[t] = s * s * s; Cs[t] = cs;
        gS2[b][t] = s * s; gS3[b][t] = s * s * s; gCs[b][t] = cs;
    }
    __syncthreads();

    for (int c = t; c < DD * NN; c += 256) {
        int d = c >> 5, i = c & 31;
        float a = As[d][i];
        A3[d][i] = a * a * a;
        SA[d][i] = S2[d] * a;
        gA[b][c] = a;
    }
    __syncthreads();

    // folded per-(d,o) coefficient matrices
    for (int c = t; c < DD * 32; c += 256) {
        int d = c >> 5;
        const float* e = eq + (size_t)c * 12;
        float4 e03 = *(const float4*)(e);
        float  e4  = e[4];
        gC0[b][c] = e03.x;
        gC1[b][c] = e03.y * S[d];
        gC2[b][c] = e03.z * S[d];
        gC3[b][c] = e03.w * S[d];
        gC4[b][c] = e4    * S2[d];
    }

    // const[o] = sum_d (e7 * S3[d] + e11 * Cs[d]) + eq_bias[o]   (deterministic order)
    if (t < 32) {
        const int o = t;
        float acc = 0.0f;
        #pragma unroll
        for (int d = 0; d < 32; d++) {
            const float* e = eq + ((size_t)(d * 32 + o)) * 12;
            acc = fmaf(e[7], S3[d], acc);
            acc = fmaf(e[11], Cs[d], acc);
        }
        gConst[b][o] = acc + eqb[o];
    }
    __syncthreads();

    // Bi[o][i] = sum_d (e6 * S^2 A + e8 * A^3)
    for (int c = t; c < DD * 32; c += 256) {
        E0[c >> 5][c & 31] = eq[(size_t)c * 12 + 6];
        E1[c >> 5][c & 31] = eq[(size_t)c * 12 + 8];
    }
    __syncthreads();
    for (int c = t; c < 32 * NN; c += 256) {
        int o = c >> 5, i = c & 31;
        float acc = 0.0f;
        #pragma unroll
        for (int d = 0; d < 32; d++) acc += E0[d][o] * SA[d][i] + E1[d][o] * A3[d][i];
        gBi[b][c] = acc;
    }
    __syncthreads();

    // Bj[o][j] = sum_d (e5 * S^2 A + e9 * A^3)
    for (int c = t; c < DD * 32; c += 256) {
        E0[c >> 5][c & 31] = eq[(size_t)c * 12 + 5];
        E1[c >> 5][c & 31] = eq[(size_t)c * 12 + 9];
    }
    __syncthreads();
    for (int c = t; c < 32 * NN; c += 256) {
        int o = c >> 5, j = c & 31;
        float acc = 0.0f;
        #pragma unroll
        for (int d = 0; d < 32; d++) acc += E0[d][o] * SA[d][j] + E1[d][o] * A3[d][j];
        gBj[b][c] = acc;
    }
    __syncthreads();

    // Tk[o][k] = sum_d e10 * A^3
    for (int c = t; c < DD * 32; c += 256) {
        E0[c >> 5][c & 31] = eq[(size_t)c * 12 + 10];
    }
    __syncthreads();
    for (int c = t; c < 32 * NN; c += 256) {
        int o = c >> 5, k = c & 31;
        float acc = 0.0f;
        #pragma unroll
        for (int d = 0; d < 32; d++) acc += E0[d][o] * A3[d][k];
        gTk[b][c] = acc;
    }
}

// ---------------- main kernel: one block per (b, i) ----------------
__global__ __launch_bounds__(256) void main_kernel(
    const float* __restrict__ fc_w, const float* __restrict__ fc_b)
{
    const int blk = blockIdx.x;
    const int b = blk >> 5, i = blk & 31;
    const int t = threadIdx.x;

    __shared__ __align__(16) float As[32][32];     // A[d][k]
    __shared__ __align__(16) float Ps[32][32];     // P[d][o] = c0*A_i + c1m
    __shared__ __align__(16) float Ts[32][32];     // temp (Q, then c3i)
    __shared__ __align__(16) float Rk[32][32];     // Rk[o][k] = Q^T A + Tk
    __shared__ __align__(16) float BaseT[32][32];  // BaseT[j][o]
    __shared__ __align__(16) float Fw[32][32];     // fc_w[o][f]
    __shared__ __align__(16) float Yr[4][32][32];  // relu(y) per j-group
    __shared__ __align__(16) float Part[256][4];   // per-thread partials (deterministic)
    __shared__ float fb[32];

    for (int c = t; c < 1024; c += 256) {
        As[c >> 5][c & 31] = gA[b][c];
        Fw[c >> 5][c & 31] = fc_w[c];
    }
    if (t < 32) fb[t] = fc_b[t];
    __syncthreads();

    // P[d][o] = c0*A_i + c1*S  ;  Q[d][o] = c2*S*A_i + c4*S^2  (in Ts)
    for (int c = t; c < 1024; c += 256) {
        int d = c >> 5;
        float ai = As[d][i];
        Ps[d][c & 31] = fmaf(gC0[b][c], ai, gC1[b][c]);
        Ts[d][c & 31] = fmaf(gC2[b][c], ai, gC4[b][c]);
    }
    __syncthreads();

    // Rk[o][k] = sum_d Q[d][o] * A[d][k] + Tk[o][k]
    for (int c = t; c < 1024; c += 256) {
        int o = c >> 5, k = c & 31;
        float acc = gTk[b][c];
        #pragma unroll
        for (int d = 0; d < 32; d++) acc = fmaf(Ts[d][o], As[d][k], acc);
        Rk[o][k] = acc;
    }
    __syncthreads();

    // Ts <- c3*S*A_i  [d][o]
    for (int c = t; c < 1024; c += 256) {
        int d = c >> 5;
        Ts[d][c & 31] = gC3[b][c] * As[d][i];
    }
    __syncthreads();

    // BaseT[j][o] = sum_d Ts[d][o]*A[d][j] + Bj[o][j] + Bi[o][i] + const[o]
    for (int c = t; c < 1024; c += 256) {
        int j = c >> 5, o = c & 31;
        float acc = gBj[b][o * 32 + j] + gBi[b][o * 32 + i] + gConst[b][o];
        #pragma unroll
        for (int d = 0; d < 32; d++) acc = fmaf(Ts[d][o], As[d][j], acc);
        BaseT[j][o] = acc;
    }
    __syncthreads();

    // tile assignment: 4 j's in flight, 64 threads per j; each thread: 4o x 4k tile
    const int jg = t >> 6;          // 0..3
    const int s  = t & 63;
    const int kt = s & 7, ot = s >> 3;
    const int k0 = kt * 4, o0 = ot * 4;

    float accL0 = 0.0f, accL1 = 0.0f, accL2 = 0.0f, accL3 = 0.0f;

    for (int jb = 0; jb < 8; jb++) {
        const int j = jb * 4 + jg;

        // ---- GEMM1: y[o,k] = sum_d (P[d,o]*A[d,j]) * A[d,k] + Rk[o,k] + BaseT[j,o]
        float y[4][4];
        {
            float4 bse = *(const float4*)&BaseT[j][o0];
            float bb[4] = { bse.x, bse.y, bse.z, bse.w };
            #pragma unroll
            for (int oi = 0; oi < 4; oi++) {
                float4 r = *(const float4*)&Rk[o0 + oi][k0];
                y[oi][0] = r.x + bb[oi]; y[oi][1] = r.y + bb[oi];
                y[oi][2] = r.z + bb[oi]; y[oi][3] = r.w + bb[oi];
            }
        }
        #pragma unroll
        for (int d = 0; d < 32; d++) {
            float aj = As[d][j];
            float4 a4 = *(const float4*)&As[d][k0];
            float4 p4 = *(const float4*)&Ps[d][o0];
            float a0 = a4.x * aj, a1 = a4.y * aj, a2 = a4.z * aj, a3 = a4.w * aj;
            y[0][0] = fmaf(p4.x, a0, y[0][0]); y[0][1] = fmaf(p4.x, a1, y[0][1]);
            y[0][2] = fmaf(p4.x, a2, y[0][2]); y[0][3] = fmaf(p4.x, a3, y[0][3]);
            y[1][0] = fmaf(p4.y, a0, y[1][0]); y[1][1] = fmaf(p4.y, a1, y[1][1]);
            y[1][2] = fmaf(p4.y, a2, y[1][2]); y[1][3] = fmaf(p4.y, a3, y[1][3]);
            y[2][0] = fmaf(p4.z, a0, y[2][0]); y[2][1] = fmaf(p4.z, a1, y[2][1]);
            y[2][2] = fmaf(p4.z, a2, y[2][2]); y[2][3] = fmaf(p4.z, a3, y[2][3]);
            y[3][0] = fmaf(p4.w, a0, y[3][0]); y[3][1] = fmaf(p4.w, a1, y[3][1]);
            y[3][2] = fmaf(p4.w, a2, y[3][2]); y[3][3] = fmaf(p4.w, a3, y[3][3]);
        }
        #pragma unroll
        for (int oi = 0; oi < 4; oi++) {
            float4 v;
            v.x = fmaxf(y[oi][0], 0.0f); v.y = fmaxf(y[oi][1], 0.0f);
            v.z = fmaxf(y[oi][2], 0.0f); v.w = fmaxf(y[oi][3], 0.0f);
            *(float4*)&Yr[jg][o0 + oi][k0] = v;
        }
        __syncthreads();

        // ---- GEMM2: z[f,k] = relu(sum_o fc_w[o,f]*Yr[o,k] + fc_b[f]); accumulate over k
        float z[4][4];
        {
            float4 fb4 = *(const float4*)&fb[o0];
            float fbv[4] = { fb4.x, fb4.y, fb4.z, fb4.w };
            #pragma unroll
            for (int fi = 0; fi < 4; fi++) {
                z[fi][0] = fbv[fi]; z[fi][1] = fbv[fi]; z[fi][2] = fbv[fi]; z[fi][3] = fbv[fi];
            }
        }
        #pragma unroll
        for (int o = 0; o < 32; o++) {
            float4 w4 = *(const float4*)&Fw[o][o0];
            float4 y4 = *(const float4*)&Yr[jg][o][k0];
            z[0][0] = fmaf(w4.x, y4.x, z[0][0]); z[0][1] = fmaf(w4.x, y4.y, z[0][1]);
            z[0][2] = fmaf(w4.x, y4.z, z[0][2]); z[0][3] = fmaf(w4.x, y4.w, z[0][3]);
            z[1][0] = fmaf(w4.y, y4.x, z[1][0]); z[1][1] = fmaf(w4.y, y4.y, z[1][1]);
            z[1][2] = fmaf(w4.y, y4.z, z[1][2]); z[1][3] = fmaf(w4.y, y4.w, z[1][3]);
            z[2][0] = fmaf(w4.z, y4.x, z[2][0]); z[2][1] = fmaf(w4.z, y4.y, z[2][1]);
            z[2][2] = fmaf(w4.z, y4.z, z[2][2]); z[2][3] = fmaf(w4.z, y4.w, z[2][3]);
            z[3][0] = fmaf(w4.w, y4.x, z[3][0]); z[3][1] = fmaf(w4.w, y4.y, z[3][1]);
            z[3][2] = fmaf(w4.w, y4.z, z[3][2]); z[3][3] = fmaf(w4.w, y4.w, z[3][3]);
        }
        accL0 += fmaxf(z[0][0], 0.0f) + fmaxf(z[0][1], 0.0f) + fmaxf(z[0][2], 0.0f) + fmaxf(z[0][3], 0.0f);
        accL1 += fmaxf(z[1][0], 0.0f) + fmaxf(z[1][1], 0.0f) + fmaxf(z[1][2], 0.0f) + fmaxf(z[1][3], 0.0f);
        accL2 += fmaxf(z[2][0], 0.0f) + fmaxf(z[2][1], 0.0f) + fmaxf(z[2][2], 0.0f) + fmaxf(z[2][3], 0.0f);
        accL3 += fmaxf(z[3][0], 0.0f) + fmaxf(z[3][1], 0.0f) + fmaxf(z[3][2], 0.0f) + fmaxf(z[3][3], 0.0f);
        __syncthreads();
    }

    // deterministic block reduction: fixed order over (jg, kt) for each o
    Part[t][0] = accL0; Part[t][1] = accL1; Part[t][2] = accL2; Part[t][3] = accL3;
    __syncthreads();
    if (t < 32) {
        const int o = t;
        const int otg = o >> 2, oi = o & 3;
        float acc = 0.0f;
        #pragma unroll
        for (int g = 0; g < 4; g++)
            #pragma unroll
            for (int kk = 0; kk < 8; kk++)
                acc += Part[g * 64 + otg * 8 + kk][oi];
        gPart[b][i][o] = acc;
    }
}

// ---------------- final head: out[b] = relu(sum_i part) @ out_w + out_b ----------------
__global__ __launch_bounds__(256) void final_kernel(
    const float* __restrict__ out_w, const float* __restrict__ out_b, float* __restrict__ out)
{
    int t = threadIdx.x;
    int b = t >> 5, o = t & 31;
    float acc = 0.0f;
    #pragma unroll
    for (int i = 0; i < NN; i++) acc += gPart[b][i][o];
    float v = fmaxf(acc, 0.0f) * out_w[o];
    #pragma unroll
    for (int off = 16; off; off >>= 1) v += __shfl_down_sync(0xffffffffu, v, off);
    if (o == 0) out[b] = v + out_b[0];
}

extern "C" void kernel_launch(void* const* d_in, const int* in_sizes, int n_in,
                              void* d_out, int out_size)
{
    const float* x    = (const float*)d_in[0];
    const float* W1   = (const float*)d_in[1];
    const float* b1   = (const float*)d_in[2];
    const float* W2   = (const float*)d_in[3];
    const float* b2   = (const float*)d_in[4];
    const float* eq   = (const float*)d_in[5];
    const float* eqb  = (const float*)d_in[6];
    const float* fcw  = (const float*)d_in[7];
    const float* fcb  = (const float*)d_in[8];
    const float* outw = (const float*)d_in[9];
    const float* outb = (const float*)d_in[10];
    float* out = (float*)d_out;

    precompute_kernel<<<BATCH, 256>>>(x, W1, b1, W2, b2, eq, eqb);
    main_kernel<<<BATCH * NN, 256>>>(fcw, fcb);
    final_kernel<<<1, 256>>>(outw, outb, out);
}

// round 3
// speedup vs baseline: 1.1528x; 1.1528x over previous
#include <cuda_runtime.h>

#define BATCH 8
#define NN    32

// deterministic partial sums per (b, i, o)
__device__ float gPart[BATCH][NN][32];

typedef unsigned long long u64;

__device__ __forceinline__ u64 pk2(float lo, float hi) {
    u64 r; asm("mov.b64 %0, {%1, %2};" : "=l"(r) : "f"(lo), "f"(hi)); return r;
}
__device__ __forceinline__ void upk2(u64 v, float& lo, float& hi) {
    asm("mov.b64 {%0, %1}, %2;" : "=f"(lo), "=f"(hi) : "l"(v));
}
__device__ __forceinline__ u64 fma2(u64 a, u64 b, u64 c) {
    u64 d; asm("fma.rn.f32x2 %0, %1, %2, %3;" : "=l"(d) : "l"(a), "l"(b), "l"(c)); return d;
}
__device__ __forceinline__ u64 mul2(u64 a, u64 b) {
    u64 d; asm("mul.rn.f32x2 %0, %1, %2;" : "=l"(d) : "l"(a), "l"(b)); return d;
}

// ---------------- fused kernel: one block per (b, i); recomputes per-batch tables ----------------
__global__ __launch_bounds__(256, 2) void fused_kernel(
    const float* __restrict__ x,  const float* __restrict__ W1, const float* __restrict__ b1,
    const float* __restrict__ W2, const float* __restrict__ b2,
    const float* __restrict__ eq, const float* __restrict__ eqb,
    const float* __restrict__ fc_w, const float* __restrict__ fc_b)
{
    const int b = blockIdx.x >> 5, i = blockIdx.x & 31;
    const int t = threadIdx.x;

    __shared__ __align__(16) float As[1024];     // A[d][k]
    __shared__ __align__(16) float Ps[1024];     // temp E-matrix, later P[d][o]
    __shared__ __align__(16) float Qm[1024];     // temp M-matrix [d][o]
    __shared__ __align__(16) float Rk[1024];     // Rk[o][k]
    __shared__ __align__(16) float BaseT[1024];  // BaseT[j][o]
    __shared__ __align__(16) float Fwm[1024];    // fc_w[o][f]
    __shared__ __align__(16) float Yrs[4096];    // per-group relu(y) tiles; also scratch
    __shared__ __align__(16) float Prt[1024];    // staging (x,W1), later per-thread partials
    __shared__ float Sd[32], S2d[32], Csd[32], BiC[32], fbv[32], Ai[32];

    float* W2S = Yrs;          // [32][33] padded transpose of W2
    float* h1  = Yrs + 1056;   // [32][33] padded
    float* A3  = Yrs + 2112;   // [32][32]
    float* xS  = Prt;          // 512
    float* W1S = Prt + 512;    // 512

    // ---- stage small tensors ----
    for (int c = t; c < 512; c += 256) { xS[c] = x[b * 512 + c]; W1S[c] = W1[c]; }
    for (int c = t; c < 1024; c += 256) {
        W2S[(c & 31) * 33 + (c >> 5)] = W2[c];   // W2S[d][e] = W2[e][d]
        Fwm[c] = fc_w[c];
    }
    if (t < 32) fbv[t] = fc_b[t];
    __syncthreads();

    // ---- h1[i][d] = relu(x @ W1 + b1), padded row 33 ----
    for (int c = t; c < 1024; c += 256) {
        int ii = c >> 5, d = c & 31;
        float acc = b1[d];
        #pragma unroll
        for (int e = 0; e < 16; e++) acc = fmaf(xS[ii * 16 + e], W1S[e * 32 + d], acc);
        h1[ii * 33 + d] = fmaxf(acc, 0.0f);
    }
    __syncthreads();

    // ---- As[d][ii] = relu(h1 @ W2 + b2), transposed ----
    for (int c = t; c < 1024; c += 256) {
        int d = c >> 5, ii = c & 31;
        float acc = b2[d];
        #pragma unroll
        for (int e = 0; e < 32; e++) acc = fmaf(h1[ii * 33 + e], W2S[d * 33 + e], acc);
        As[d * 32 + ii] = fmaxf(acc, 0.0f);
    }
    __syncthreads();

    // ---- A3, S, S^2, sum(A^3), Ai ----
    if (t < 32) Ai[t] = As[t * 32 + i];
    {
        int d = t >> 3, r = t & 7;
        float s = 0.0f, cs = 0.0f;
        #pragma unroll
        for (int q = 0; q < 4; q++) {
            float a = As[d * 32 + r * 4 + q];
            float a3 = a * a * a;
            s += a; cs += a3;
            A3[d * 32 + r * 4 + q] = a3;
        }
        #pragma unroll
        for (int off = 4; off; off >>= 1) {
            s  += __shfl_down_sync(0xffffffffu, s,  off, 8);
            cs += __shfl_down_sync(0xffffffffu, cs, off, 8);
        }
        if (r == 0) { Sd[d] = s; S2d[d] = s * s; Csd[d] = cs; }
    }
    __syncthreads();

    // ---- BiC[o] = Bi_i[o] + const[o] + eq_bias[o]  (deterministic d order) ----
    if (t < 32) {
        float acc = eqb[t];
        #pragma unroll
        for (int d = 0; d < 32; d++) {
            const float* e = eq + (size_t)(d * 32 + t) * 12;
            float ai = Ai[d];
            acc = fmaf(e[6], S2d[d] * ai, acc);
            acc = fmaf(e[8], ai * ai * ai, acc);
            acc = fmaf(e[7], S2d[d] * Sd[d], acc);
            acc = fmaf(e[11], Csd[d], acc);
        }
        BiC[t] = acc;
    }

    // ---- Rk[o][k] = sum_d (e2*S*ai + e4*S^2)[d,o]*A[d,k] + e10[d,o]*A3[d,k] ----
    for (int c = t; c < 1024; c += 256) {
        int d = c >> 5;
        const float* e = eq + (size_t)c * 12;
        Qm[c] = Sd[d] * fmaf(e[2], Ai[d], e[4] * Sd[d]);
        Ps[c] = e[10];
    }
    __syncthreads();
    for (int c = t; c < 1024; c += 256) {
        int o = c >> 5, k = c & 31;
        float acc = 0.0f;
        #pragma unroll
        for (int d = 0; d < 32; d++)
            acc = fmaf(Qm[d * 32 + o], As[d * 32 + k], fmaf(Ps[d * 32 + o], A3[d * 32 + k], acc));
        Rk[c] = acc;
    }
    __syncthreads();

    // ---- BaseT[j][o] = sum_d (e3*S*ai + e5*S^2)[d,o]*A[d,j] + e9[d,o]*A3[d,j] + BiC[o] ----
    for (int c = t; c < 1024; c += 256) {
        int d = c >> 5;
        const float* e = eq + (size_t)c * 12;
        Qm[c] = Sd[d] * fmaf(e[3], Ai[d], e[5] * Sd[d]);
        Ps[c] = e[9];
    }
    __syncthreads();
    for (int c = t; c < 1024; c += 256) {
        int j = c >> 5, o = c & 31;
        float acc = BiC[o];
        #pragma unroll
        for (int d = 0; d < 32; d++)
            acc = fmaf(Qm[d * 32 + o], As[d * 32 + j], fmaf(Ps[d * 32 + o], A3[d * 32 + j], acc));
        BaseT[c] = acc;
    }
    __syncthreads();

    // ---- Ps[d][o] = e0*ai + e1*S ----
    for (int c = t; c < 1024; c += 256) {
        int d = c >> 5;
        const float* e = eq + (size_t)c * 12;
        Ps[c] = fmaf(e[0], Ai[d], e[1] * Sd[d]);
    }
    __syncthreads();

    // ---- main loops: 4 j-groups of 64 threads; thread tile = 4o x 4k (k packed in f32x2) ----
    const int jg = t >> 6;
    const int s  = t & 63;
    const int k0 = (s & 7) * 4, o0 = (s >> 3) * 4;
    float* Yg = Yrs + jg * 1024;
    const int barid = 1 + jg;

    float acc0 = 0.0f, acc1 = 0.0f, acc2 = 0.0f, acc3 = 0.0f;

    #pragma unroll 1
    for (int jb = 0; jb < 8; jb++) {
        const int j = jb * 4 + jg;

        // GEMM1: y[o,k] = sum_d P[d,o]*(A[d,j]*A[d,k]) + Rk[o,k] + BaseT[j,o]
        u64 y[4][2];
        {
            float4 bse = *(const float4*)&BaseT[j * 32 + o0];
            float bb[4] = { bse.x, bse.y, bse.z, bse.w };
            #pragma unroll
            for (int oi = 0; oi < 4; oi++) {
                float4 r = *(const float4*)&Rk[(o0 + oi) * 32 + k0];
                y[oi][0] = pk2(r.x + bb[oi], r.y + bb[oi]);
                y[oi][1] = pk2(r.z + bb[oi], r.w + bb[oi]);
            }
        }
        #pragma unroll
        for (int d = 0; d < 32; d++) {
            float aj = As[d * 32 + j];
            ulonglong2 a2 = *(const ulonglong2*)&As[d * 32 + k0];
            u64 ajd = pk2(aj, aj);
            u64 s01 = mul2(a2.x, ajd), s23 = mul2(a2.y, ajd);
            float4 p4 = *(const float4*)&Ps[d * 32 + o0];
            u64 pd;
            pd = pk2(p4.x, p4.x); y[0][0] = fma2(pd, s01, y[0][0]); y[0][1] = fma2(pd, s23, y[0][1]);
            pd = pk2(p4.y, p4.y); y[1][0] = fma2(pd, s01, y[1][0]); y[1][1] = fma2(pd, s23, y[1][1]);
            pd = pk2(p4.z, p4.z); y[2][0] = fma2(pd, s01, y[2][0]); y[2][1] = fma2(pd, s23, y[2][1]);
            pd = pk2(p4.w, p4.w); y[3][0] = fma2(pd, s01, y[3][0]); y[3][1] = fma2(pd, s23, y[3][1]);
        }
        #pragma unroll
        for (int oi = 0; oi < 4; oi++) {
            float v0, v1, v2, v3;
            upk2(y[oi][0], v0, v1);
            upk2(y[oi][1], v2, v3);
            float4 v;
            v.x = fmaxf(v0, 0.0f); v.y = fmaxf(v1, 0.0f);
            v.z = fmaxf(v2, 0.0f); v.w = fmaxf(v3, 0.0f);
            *(float4*)&Yg[(o0 + oi) * 32 + k0] = v;
        }
        asm volatile("bar.sync %0, %1;" :: "r"(barid), "r"(64) : "memory");

        // GEMM2: z[f,k] = relu(sum_o fc_w[o,f]*Yr[o,k] + fc_b[f]); accumulate over k
        u64 z[4][2];
        {
            u64 zi0 = pk2(fbv[o0 + 0], fbv[o0 + 0]);
            u64 zi1 = pk2(fbv[o0 + 1], fbv[o0 + 1]);
            u64 zi2 = pk2(fbv[o0 + 2], fbv[o0 + 2]);
            u64 zi3 = pk2(fbv[o0 + 3], fbv[o0 + 3]);
            z[0][0] = zi0; z[0][1] = zi0;
            z[1][0] = zi1; z[1][1] = zi1;
            z[2][0] = zi2; z[2][1] = zi2;
            z[3][0] = zi3; z[3][1] = zi3;
        }
        #pragma unroll
        for (int o = 0; o < 32; o++) {
            float4 w4 = *(const float4*)&Fwm[o * 32 + o0];
            ulonglong2 y2 = *(const ulonglong2*)&Yg[o * 32 + k0];
            u64 wd;
            wd = pk2(w4.x, w4.x); z[0][0] = fma2(wd, y2.x, z[0][0]); z[0][1] = fma2(wd, y2.y, z[0][1]);
            wd = pk2(w4.y, w4.y); z[1][0] = fma2(wd, y2.x, z[1][0]); z[1][1] = fma2(wd, y2.y, z[1][1]);
            wd = pk2(w4.z, w4.z); z[2][0] = fma2(wd, y2.x, z[2][0]); z[2][1] = fma2(wd, y2.y, z[2][1]);
            wd = pk2(w4.w, w4.w); z[3][0] = fma2(wd, y2.x, z[3][0]); z[3][1] = fma2(wd, y2.y, z[3][1]);
        }
        {
            float v0, v1, v2, v3;
            upk2(z[0][0], v0, v1); upk2(z[0][1], v2, v3);
            acc0 += fmaxf(v0, 0.0f) + fmaxf(v1, 0.0f) + fmaxf(v2, 0.0f) + fmaxf(v3, 0.0f);
            upk2(z[1][0], v0, v1); upk2(z[1][1], v2, v3);
            acc1 += fmaxf(v0, 0.0f) + fmaxf(v1, 0.0f) + fmaxf(v2, 0.0f) + fmaxf(v3, 0.0f);
            upk2(z[2][0], v0, v1); upk2(z[2][1], v2, v3);
            acc2 += fmaxf(v0, 0.0f) + fmaxf(v1, 0.0f) + fmaxf(v2, 0.0f) + fmaxf(v3, 0.0f);
            upk2(z[3][0], v0, v1); upk2(z[3][1], v2, v3);
            acc3 += fmaxf(v0, 0.0f) + fmaxf(v1, 0.0f) + fmaxf(v2, 0.0f) + fmaxf(v3, 0.0f);
        }
        asm volatile("bar.sync %0, %1;" :: "r"(barid), "r"(64) : "memory");
    }

    // ---- deterministic block reduction ----
    Prt[t * 4 + 0] = acc0; Prt[t * 4 + 1] = acc1;
    Prt[t * 4 + 2] = acc2; Prt[t * 4 + 3] = acc3;
    __syncthreads();
    if (t < 32) {
        const int otg = t >> 2, oi = t & 3;
        float acc = 0.0f;
        #pragma unroll
        for (int g = 0; g < 4; g++)
            #pragma unroll
            for (int kk = 0; kk < 8; kk++)
                acc += Prt[(g * 64 + otg * 8 + kk) * 4 + oi];
        gPart[b][i][t] = acc;
    }
}

// ---------------- final head: out[b] = relu(sum_i part) @ out_w + out_b ----------------
__global__ __launch_bounds__(256) void final_kernel(
    const float* __restrict__ out_w, const float* __restrict__ out_b, float* __restrict__ out)
{
    int t = threadIdx.x;
    int b = t >> 5, o = t & 31;
    float acc = 0.0f;
    #pragma unroll
    for (int i = 0; i < NN; i++) acc += gPart[b][i][o];
    float v = fmaxf(acc, 0.0f) * out_w[o];
    #pragma unroll
    for (int off = 16; off; off >>= 1) v += __shfl_down_sync(0xffffffffu, v, off);
    if (o == 0) out[b] = v + out_b[0];
}

extern "C" void kernel_launch(void* const* d_in, const int* in_sizes, int n_in,
                              void* d_out, int out_size)
{
    const float* x    = (const float*)d_in[0];
    const float* W1   = (const float*)d_in[1];
    const float* b1   = (const float*)d_in[2];
    const float* W2   = (const float*)d_in[3];
    const float* b2   = (const float*)d_in[4];
    const float* eq   = (const float*)d_in[5];
    const float* eqb  = (const float*)d_in[6];
    const float* fcw  = (const float*)d_in[7];
    const float* fcb  = (const float*)d_in[8];
    const float* outw = (const float*)d_in[9];
    const float* outb = (const float*)d_in[10];
    float* out = (float*)d_out;

    fused_kernel<<<BATCH * NN, 256>>>(x, W1, b1, W2, b2, eq, eqb, fcw, fcb);
    final_kernel<<<1, 256>>>(outw, outb, out);
}

// round 4
// speedup vs baseline: 1.2862x; 1.1158x over previous
#include <cuda_runtime.h>

#define BATCH 8
#define NN    32

__device__ float gPart[BATCH][NN][32];
__device__ unsigned int gCount = 0;

typedef unsigned long long u64;

__device__ __forceinline__ u64 pk2(float lo, float hi) {
    u64 r; asm("mov.b64 %0, {%1, %2};" : "=l"(r) : "f"(lo), "f"(hi)); return r;
}
__device__ __forceinline__ void upk2(u64 v, float& lo, float& hi) {
    asm("mov.b64 {%0, %1}, %2;" : "=f"(lo), "=f"(hi) : "l"(v));
}
__device__ __forceinline__ u64 fma2(u64 a, u64 b, u64 c) {
    u64 d; asm("fma.rn.f32x2 %0, %1, %2, %3;" : "=l"(d) : "l"(a), "l"(b), "l"(c)); return d;
}
__device__ __forceinline__ u64 mul2(u64 a, u64 b) {
    u64 d; asm("mul.rn.f32x2 %0, %1, %2;" : "=l"(d) : "l"(a), "l"(b)); return d;
}

// ---------------- fused kernel: one block per (b, i) ----------------
__global__ __launch_bounds__(256, 2) void fused_kernel(
    const float* __restrict__ x,  const float* __restrict__ W1, const float* __restrict__ b1,
    const float* __restrict__ W2, const float* __restrict__ b2,
    const float* __restrict__ eq, const float* __restrict__ eqb,
    const float* __restrict__ fc_w, const float* __restrict__ fc_b,
    const float* __restrict__ out_w, const float* __restrict__ out_b,
    float* __restrict__ out)
{
    const int b = blockIdx.x >> 5, i = blockIdx.x & 31;
    const int t = threadIdx.x;

    // persistent shared
    __shared__ __align__(16) float As_[1024];    // A[d][k]
    __shared__ __align__(16) float PsM[1024];    // P[d][o] = e0*ai + e1*S
    __shared__ __align__(16) float Rk_[1024];    // Rk[o][k]
    __shared__ __align__(16) float BaseT[1024];  // BaseT[j][o]
    __shared__ __align__(16) float Fwm[1024];    // fc_w[o][f]
    // overlay scratch region (phased)
    __shared__ __align__(16) float Reg[6144];
    __shared__ float Sd[32], S2d[32], Csd[32], BiC[32], fbv[32], Ai[32];
    __shared__ unsigned int isLast;

    // phase A-C overlay
    float* W2S = Reg;           // [32][33] W2 transposed, padded
    float* h1  = Reg + 1056;    // [32][33]
    float* xS  = Reg + 2112;    // 512
    float* W1S = Reg + 2624;    // 512
    // phase D-G overlay
    float* A3  = Reg;           // [d][k] 1024
    float* QmR = Reg + 1024;
    float* PsR = Reg + 2048;
    float* QmB = Reg + 3072;
    float* PsB = Reg + 4096;
    float* Cn  = Reg + 5120;
    // main-loop overlay
    //   Yg tiles: Reg[jg*1024 .. +1023]
    //   Prt:      Reg + 4096 (per-thread partials, 1024)

    // ---- phase A: stage small tensors ----
    for (int c = t; c < 512; c += 256) { xS[c] = x[b * 512 + c]; W1S[c] = W1[c]; }
    for (int c = t; c < 1024; c += 256) {
        W2S[(c & 31) * 33 + (c >> 5)] = W2[c];
        Fwm[c] = fc_w[c];
    }
    if (t < 32) fbv[t] = fc_b[t];
    __syncthreads();

    // ---- phase B: h1 = relu(x @ W1 + b1) ----
    for (int c = t; c < 1024; c += 256) {
        int ii = c >> 5, d = c & 31;
        float acc = b1[d];
        #pragma unroll
        for (int e = 0; e < 16; e++) acc = fmaf(xS[ii * 16 + e], W1S[e * 32 + d], acc);
        h1[ii * 33 + d] = fmaxf(acc, 0.0f);
    }
    __syncthreads();

    // ---- phase C: As[d][ii] = relu(h1 @ W2 + b2) transposed ----
    for (int c = t; c < 1024; c += 256) {
        int d = c >> 5, ii = c & 31;
        float acc = b2[d];
        #pragma unroll
        for (int e = 0; e < 32; e++) acc = fmaf(h1[ii * 33 + e], W2S[d * 33 + e], acc);
        As_[d * 32 + ii] = fmaxf(acc, 0.0f);
    }
    __syncthreads();

    // ---- phase D: A3, per-d stats, Ai ----
    if (t < 32) Ai[t] = As_[t * 32 + i];
    {
        int d = t >> 3, r = t & 7;
        float s = 0.0f, cs = 0.0f;
        #pragma unroll
        for (int q = 0; q < 4; q++) {
            float a = As_[d * 32 + r * 4 + q];
            float a3 = a * a * a;
            s += a; cs += a3;
            A3[d * 32 + r * 4 + q] = a3;
        }
        #pragma unroll
        for (int off = 4; off; off >>= 1) {
            s  += __shfl_down_sync(0xffffffffu, s,  off, 8);
            cs += __shfl_down_sync(0xffffffffu, cs, off, 8);
        }
        if (r == 0) { Sd[d] = s; S2d[d] = s * s; Csd[d] = cs; }
    }
    __syncthreads();

    // ---- phase E: single-pass eq fold ----
    for (int c = t; c < 1024; c += 256) {
        int d = c >> 5;
        const float* e = eq + (size_t)c * 12;
        float4 e03  = *(const float4*)(e);
        float4 e47  = *(const float4*)(e + 4);
        float4 e811 = *(const float4*)(e + 8);
        float ai = Ai[d], s = Sd[d], s2 = S2d[d];
        PsM[c] = fmaf(e03.x, ai, e03.y * s);
        QmR[c] = fmaf(s * e03.z, ai, e47.x * s2);
        PsR[c] = e811.z;   // e10
        QmB[c] = fmaf(s * e03.w, ai, e47.y * s2);
        PsB[c] = e811.y;   // e9
        Cn[c]  = fmaf(e47.z, s2 * ai, fmaf(e811.x, ai * ai * ai,
                 fmaf(e47.w, s2 * s, e811.w * Csd[d])));
    }
    __syncthreads();

    // ---- phase F: Rk + BiC ----
    for (int c = t; c < 1024; c += 256) {
        int o = c >> 5, k = c & 31;
        float acc = 0.0f;
        #pragma unroll
        for (int d = 0; d < 32; d++)
            acc = fmaf(QmR[d * 32 + o], As_[d * 32 + k], fmaf(PsR[d * 32 + o], A3[d * 32 + k], acc));
        Rk_[c] = acc;
    }
    if (t < 32) {
        float acc = eqb[t];
        #pragma unroll
        for (int d = 0; d < 32; d++) acc += Cn[d * 32 + t];
        BiC[t] = acc;
    }
    __syncthreads();

    // ---- phase G: BaseT[j][o] ----
    for (int c = t; c < 1024; c += 256) {
        int j = c >> 5, o = c & 31;
        float acc = BiC[o];
        #pragma unroll
        for (int d = 0; d < 32; d++)
            acc = fmaf(QmB[d * 32 + o], As_[d * 32 + j], fmaf(PsB[d * 32 + o], A3[d * 32 + j], acc));
        BaseT[c] = acc;
    }
    __syncthreads();

    // ---- main loops: 4 groups of 64 threads; each handles j pairs; tile 4o x 4k x 2j ----
    const int jg = t >> 6;
    const int s  = t & 63;
    const int k0 = (s & 7) * 4, o0 = (s >> 3) * 4;
    float* Yg = Reg + jg * 1024;
    float* Prt = Reg + 4096;
    const int barid = 1 + jg;

    float acc0 = 0.0f, acc1 = 0.0f, acc2 = 0.0f, acc3 = 0.0f;

    #pragma unroll 1
    for (int jb = 0; jb < 4; jb++) {
        const int j0 = jb * 8 + jg * 2;     // j1 = j0 + 1 (adjacent -> one LDS.64)

        // ---- GEMM1 for both j ----
        u64 yA[4][2], yB[4][2];
        {
            float4 bA = *(const float4*)&BaseT[j0 * 32 + o0];
            float4 bB = *(const float4*)&BaseT[(j0 + 1) * 32 + o0];
            float aA[4] = { bA.x, bA.y, bA.z, bA.w };
            float aB[4] = { bB.x, bB.y, bB.z, bB.w };
            #pragma unroll
            for (int oi = 0; oi < 4; oi++) {
                float4 r = *(const float4*)&Rk_[(o0 + oi) * 32 + k0];
                yA[oi][0] = pk2(r.x + aA[oi], r.y + aA[oi]);
                yA[oi][1] = pk2(r.z + aA[oi], r.w + aA[oi]);
                yB[oi][0] = pk2(r.x + aB[oi], r.y + aB[oi]);
                yB[oi][1] = pk2(r.z + aB[oi], r.w + aB[oi]);
            }
        }
        #pragma unroll
        for (int d = 0; d < 32; d++) {
            float2 ajp = *(const float2*)&As_[d * 32 + j0];
            ulonglong2 a2 = *(const ulonglong2*)&As_[d * 32 + k0];
            u64 ajA = pk2(ajp.x, ajp.x);
            u64 ajB = pk2(ajp.y, ajp.y);
            u64 sA01 = mul2(a2.x, ajA), sA23 = mul2(a2.y, ajA);
            u64 sB01 = mul2(a2.x, ajB), sB23 = mul2(a2.y, ajB);
            float4 p4 = *(const float4*)&PsM[d * 32 + o0];
            u64 pd;
            pd = pk2(p4.x, p4.x);
            yA[0][0] = fma2(pd, sA01, yA[0][0]); yA[0][1] = fma2(pd, sA23, yA[0][1]);
            yB[0][0] = fma2(pd, sB01, yB[0][0]); yB[0][1] = fma2(pd, sB23, yB[0][1]);
            pd = pk2(p4.y, p4.y);
            yA[1][0] = fma2(pd, sA01, yA[1][0]); yA[1][1] = fma2(pd, sA23, yA[1][1]);
            yB[1][0] = fma2(pd, sB01, yB[1][0]); yB[1][1] = fma2(pd, sB23, yB[1][1]);
            pd = pk2(p4.z, p4.z);
            yA[2][0] = fma2(pd, sA01, yA[2][0]); yA[2][1] = fma2(pd, sA23, yA[2][1]);
            yB[2][0] = fma2(pd, sB01, yB[2][0]); yB[2][1] = fma2(pd, sB23, yB[2][1]);
            pd = pk2(p4.w, p4.w);
            yA[3][0] = fma2(pd, sA01, yA[3][0]); yA[3][1] = fma2(pd, sA23, yA[3][1]);
            yB[3][0] = fma2(pd, sB01, yB[3][0]); yB[3][1] = fma2(pd, sB23, yB[3][1]);
        }

        // ---- per-j: write relu(y) tile, GEMM2, accumulate ----
        #pragma unroll
        for (int half = 0; half < 2; half++) {
            u64 (*yy)[2] = half ? yB : yA;
            #pragma unroll
            for (int oi = 0; oi < 4; oi++) {
                float v0, v1, v2, v3;
                upk2(yy[oi][0], v0, v1);
                upk2(yy[oi][1], v2, v3);
                float4 v;
                v.x = fmaxf(v0, 0.0f); v.y = fmaxf(v1, 0.0f);
                v.z = fmaxf(v2, 0.0f); v.w = fmaxf(v3, 0.0f);
                *(float4*)&Yg[(o0 + oi) * 32 + k0] = v;
            }
            asm volatile("bar.sync %0, %1;" :: "r"(barid), "r"(64) : "memory");

            u64 z[4][2];
            {
                u64 zi0 = pk2(fbv[o0 + 0], fbv[o0 + 0]);
                u64 zi1 = pk2(fbv[o0 + 1], fbv[o0 + 1]);
                u64 zi2 = pk2(fbv[o0 + 2], fbv[o0 + 2]);
                u64 zi3 = pk2(fbv[o0 + 3], fbv[o0 + 3]);
                z[0][0] = zi0; z[0][1] = zi0;
                z[1][0] = zi1; z[1][1] = zi1;
                z[2][0] = zi2; z[2][1] = zi2;
                z[3][0] = zi3; z[3][1] = zi3;
            }
            #pragma unroll
            for (int o = 0; o < 32; o++) {
                float4 w4 = *(const float4*)&Fwm[o * 32 + o0];
                ulonglong2 y2 = *(const ulonglong2*)&Yg[o * 32 + k0];
                u64 wd;
                wd = pk2(w4.x, w4.x); z[0][0] = fma2(wd, y2.x, z[0][0]); z[0][1] = fma2(wd, y2.y, z[0][1]);
                wd = pk2(w4.y, w4.y); z[1][0] = fma2(wd, y2.x, z[1][0]); z[1][1] = fma2(wd, y2.y, z[1][1]);
                wd = pk2(w4.z, w4.z); z[2][0] = fma2(wd, y2.x, z[2][0]); z[2][1] = fma2(wd, y2.y, z[2][1]);
                wd = pk2(w4.w, w4.w); z[3][0] = fma2(wd, y2.x, z[3][0]); z[3][1] = fma2(wd, y2.y, z[3][1]);
            }
            {
                float v0, v1, v2, v3;
                upk2(z[0][0], v0, v1); upk2(z[0][1], v2, v3);
                acc0 += fmaxf(v0, 0.0f) + fmaxf(v1, 0.0f) + fmaxf(v2, 0.0f) + fmaxf(v3, 0.0f);
                upk2(z[1][0], v0, v1); upk2(z[1][1], v2, v3);
                acc1 += fmaxf(v0, 0.0f) + fmaxf(v1, 0.0f) + fmaxf(v2, 0.0f) + fmaxf(v3, 0.0f);
                upk2(z[2][0], v0, v1); upk2(z[2][1], v2, v3);
                acc2 += fmaxf(v0, 0.0f) + fmaxf(v1, 0.0f) + fmaxf(v2, 0.0f) + fmaxf(v3, 0.0f);
                upk2(z[3][0], v0, v1); upk2(z[3][1], v2, v3);
                acc3 += fmaxf(v0, 0.0f) + fmaxf(v1, 0.0f) + fmaxf(v2, 0.0f) + fmaxf(v3, 0.0f);
            }
            asm volatile("bar.sync %0, %1;" :: "r"(barid), "r"(64) : "memory");
        }
    }

    // ---- deterministic block reduction ----
    Prt[t * 4 + 0] = acc0; Prt[t * 4 + 1] = acc1;
    Prt[t * 4 + 2] = acc2; Prt[t * 4 + 3] = acc3;
    __syncthreads();
    if (t < 32) {
        const int otg = t >> 2, oi = t & 3;
        float acc = 0.0f;
        #pragma unroll
        for (int g = 0; g < 4; g++)
            #pragma unroll
            for (int kk = 0; kk < 8; kk++)
                acc += Prt[(g * 64 + otg * 8 + kk) * 4 + oi];
        gPart[b][i][t] = acc;
    }
    __threadfence();
    __syncthreads();

    // ---- last block performs the final head ----
    if (t == 0) {
        unsigned int old = atomicAdd(&gCount, 1u);
        isLast = (old == (unsigned)(BATCH * NN - 1)) ? 1u : 0u;
    }
    __syncthreads();
    if (isLast) {
        __threadfence();
        const int bb = t >> 5, oo = t & 31;
        float acc = 0.0f;
        #pragma unroll
        for (int ii = 0; ii < NN; ii++) acc += gPart[bb][ii][oo];
        float v = fmaxf(acc, 0.0f) * out_w[oo];
        #pragma unroll
        for (int off = 16; off; off >>= 1) v += __shfl_down_sync(0xffffffffu, v, off);
        if (oo == 0) out[bb] = v + out_b[0];
        __syncthreads();
        if (t == 0) gCount = 0u;   // reset for next replay
    }
}

extern "C" void kernel_launch(void* const* d_in, const int* in_sizes, int n_in,
                              void* d_out, int out_size)
{
    const float* x    = (const float*)d_in[0];
    const float* W1   = (const float*)d_in[1];
    const float* b1   = (const float*)d_in[2];
    const float* W2   = (const float*)d_in[3];
    const float* b2   = (const float*)d_in[4];
    const float* eq   = (const float*)d_in[5];
    const float* eqb  = (const float*)d_in[6];
    const float* fcw  = (const float*)d_in[7];
    const float* fcb  = (const float*)d_in[8];
    const float* outw = (const float*)d_in[9];
    const float* outb = (const float*)d_in[10];
    float* out = (float*)d_out;

    fused_kernel<<<BATCH * NN, 256>>>(x, W1, b1, W2, b2, eq, eqb, fcw, fcb, outw, outb, out);
}

// round 7
// speedup vs baseline: 1.3465x; 1.0468x over previous
#include <cuda_runtime.h>

#define BATCH 8
#define NN    32

__device__ float gPart[BATCH][NN][32];
__device__ unsigned int gCount = 0;

typedef unsigned long long u64;

__device__ __forceinline__ u64 pk2(float lo, float hi) {
    u64 r; asm("mov.b64 %0, {%1, %2};" : "=l"(r) : "f"(lo), "f"(hi)); return r;
}
__device__ __forceinline__ void upk2(u64 v, float& lo, float& hi) {
    asm("mov.b64 {%0, %1}, %2;" : "=f"(lo), "=f"(hi) : "l"(v));
}
__device__ __forceinline__ u64 fma2(u64 a, u64 b, u64 c) {
    u64 d; asm("fma.rn.f32x2 %0, %1, %2, %3;" : "=l"(d) : "l"(a), "l"(b), "l"(c)); return d;
}
__device__ __forceinline__ u64 mul2(u64 a, u64 b) {
    u64 d; asm("mul.rn.f32x2 %0, %1, %2;" : "=l"(d) : "l"(a), "l"(b)); return d;
}

#define YSTRIDE 36          // Yg row stride (144 B: 16B-aligned, bank-rotated)
#define YG_PER_GROUP 1152   // 32 * 36  (ONE j tile per group)
#define DYN_FLOATS 6144     // max(prologue 6144, Yg 4*1152=4608, Prt 2048) -> 24.6 KB

// ---------------- fused kernel: one block per (b, i) ----------------
__global__ __launch_bounds__(256, 2) void fused_kernel(
    const float* __restrict__ x,  const float* __restrict__ W1, const float* __restrict__ b1,
    const float* __restrict__ W2, const float* __restrict__ b2,
    const float* __restrict__ eq, const float* __restrict__ eqb,
    const float* __restrict__ fc_w, const float* __restrict__ fc_b,
    const float* __restrict__ out_w, const float* __restrict__ out_b,
    float* __restrict__ out)
{
    const int b = blockIdx.x >> 5, i = blockIdx.x & 31;
    const int t = threadIdx.x;

    // persistent static shared (~20.8 KB)
    __shared__ __align__(16) float As_[1024];    // A[d][k]
    __shared__ __align__(16) float PsM[1024];    // P[d][o]
    __shared__ __align__(16) float Rk_[1024];    // Rk[o][k]
    __shared__ __align__(16) float BaseT[1024];  // BaseT[j][o]
    __shared__ __align__(16) float Fwm[1024];    // fc_w[o][f]
    __shared__ float Sd[32], S2d[32], Csd[32], BiC[32], fbv[32], Ai[32];
    __shared__ unsigned int isLast;

    // dynamic shared: 6144 floats = 24576 B; total smem ~45 KB < 48 KB default
    extern __shared__ __align__(16) float dyn[];

    // prologue overlay (phases A-C)
    float* W2S = dyn;           // [32][33]
    float* h1  = dyn + 1056;    // [32][33]
    float* xS  = dyn + 2112;    // 512
    float* W1S = dyn + 2624;    // 512
    // prologue overlay (phases D-G)
    float* A3  = dyn;           // 1024
    float* QmR = dyn + 1024;
    float* PsR = dyn + 2048;
    float* QmB = dyn + 3072;
    float* PsB = dyn + 4096;
    float* Cn  = dyn + 5120;
    // main loop: Yg per group at dyn + jg*YG_PER_GROUP; epilogue: Prt = dyn

    // ---- phase A: stage small tensors ----
    for (int c = t; c < 512; c += 256) { xS[c] = x[b * 512 + c]; W1S[c] = W1[c]; }
    for (int c = t; c < 1024; c += 256) {
        W2S[(c & 31) * 33 + (c >> 5)] = W2[c];
        Fwm[c] = fc_w[c];
    }
    if (t < 32) fbv[t] = fc_b[t];
    __syncthreads();

    // ---- phase B: h1 = relu(x @ W1 + b1) ----
    for (int c = t; c < 1024; c += 256) {
        int ii = c >> 5, d = c & 31;
        float acc = b1[d];
        #pragma unroll
        for (int e = 0; e < 16; e++) acc = fmaf(xS[ii * 16 + e], W1S[e * 32 + d], acc);
        h1[ii * 33 + d] = fmaxf(acc, 0.0f);
    }
    __syncthreads();

    // ---- phase C: As[d][ii] = relu(h1 @ W2 + b2), transposed ----
    for (int c = t; c < 1024; c += 256) {
        int d = c >> 5, ii = c & 31;
        float acc = b2[d];
        #pragma unroll
        for (int e = 0; e < 32; e++) acc = fmaf(h1[ii * 33 + e], W2S[d * 33 + e], acc);
        As_[d * 32 + ii] = fmaxf(acc, 0.0f);
    }
    __syncthreads();

    // ---- phase D: A3, per-d stats, Ai ----
    if (t < 32) Ai[t] = As_[t * 32 + i];
    {
        int d = t >> 3, r = t & 7;
        float s = 0.0f, cs = 0.0f;
        #pragma unroll
        for (int q = 0; q < 4; q++) {
            float a = As_[d * 32 + r * 4 + q];
            float a3 = a * a * a;
            s += a; cs += a3;
            A3[d * 32 + r * 4 + q] = a3;
        }
        #pragma unroll
        for (int off = 4; off; off >>= 1) {
            s  += __shfl_down_sync(0xffffffffu, s,  off, 8);
            cs += __shfl_down_sync(0xffffffffu, cs, off, 8);
        }
        if (r == 0) { Sd[d] = s; S2d[d] = s * s; Csd[d] = cs; }
    }
    __syncthreads();

    // ---- phase E: single-pass eq fold ----
    for (int c = t; c < 1024; c += 256) {
        int d = c >> 5;
        const float* e = eq + (size_t)c * 12;
        float4 e03  = *(const float4*)(e);
        float4 e47  = *(const float4*)(e + 4);
        float4 e811 = *(const float4*)(e + 8);
        float ai = Ai[d], s = Sd[d], s2 = S2d[d];
        PsM[c] = fmaf(e03.x, ai, e03.y * s);
        QmR[c] = fmaf(s * e03.z, ai, e47.x * s2);
        PsR[c] = e811.z;   // e10
        QmB[c] = fmaf(s * e03.w, ai, e47.y * s2);
        PsB[c] = e811.y;   // e9
        Cn[c]  = fmaf(e47.z, s2 * ai, fmaf(e811.x, ai * ai * ai,
                 fmaf(e47.w, s2 * s, e811.w * Csd[d])));
    }
    __syncthreads();

    // ---- phase F (vectorized): Rk[o][k] ----
    {
        const int o = t >> 3, kq = (t & 7) * 4;
        u64 acc0 = 0ull, acc1 = 0ull;
        #pragma unroll
        for (int d = 0; d < 32; d++) {
            float qv = QmR[d * 32 + o], pv = PsR[d * 32 + o];
            u64 qm = pk2(qv, qv), ps = pk2(pv, pv);
            ulonglong2 as2 = *(const ulonglong2*)&As_[d * 32 + kq];
            ulonglong2 a32 = *(const ulonglong2*)&A3[d * 32 + kq];
            acc0 = fma2(qm, as2.x, fma2(ps, a32.x, acc0));
            acc1 = fma2(qm, as2.y, fma2(ps, a32.y, acc1));
        }
        float v0, v1, v2, v3;
        upk2(acc0, v0, v1); upk2(acc1, v2, v3);
        *(float4*)&Rk_[o * 32 + kq] = make_float4(v0, v1, v2, v3);
    }
    if (t < 32) {
        float acc = eqb[t];
        #pragma unroll
        for (int d = 0; d < 32; d++) acc += Cn[d * 32 + t];
        BiC[t] = acc;
    }
    __syncthreads();

    // ---- phase G (vectorized): BaseT[j][o] ----
    {
        const int j = t >> 3, oq = (t & 7) * 4;
        u64 acc0 = 0ull, acc1 = 0ull;
        #pragma unroll
        for (int d = 0; d < 32; d++) {
            float ajv = As_[d * 32 + j], a3v = A3[d * 32 + j];
            u64 ajb = pk2(ajv, ajv), a3b = pk2(a3v, a3v);
            ulonglong2 qm2 = *(const ulonglong2*)&QmB[d * 32 + oq];
            ulonglong2 ps2 = *(const ulonglong2*)&PsB[d * 32 + oq];
            acc0 = fma2(qm2.x, ajb, fma2(ps2.x, a3b, acc0));
            acc1 = fma2(qm2.y, ajb, fma2(ps2.y, a3b, acc1));
        }
        float v0, v1, v2, v3;
        upk2(acc0, v0, v1); upk2(acc1, v2, v3);
        float4 bc = *(const float4*)&BiC[oq];
        *(float4*)&BaseT[j * 32 + oq] =
            make_float4(v0 + bc.x, v1 + bc.y, v2 + bc.z, v3 + bc.w);
    }
    __syncthreads();

    // ================= main loop: 4 groups of 64 threads, j-pair per pass =================
    const int jg = t >> 6;
    const int s  = t & 63;
    // GEMM1 mapping (4o x 4k per thread, per j)
    const int k0 = (s & 7) * 4, o0 = (s >> 3) * 4;
    // GEMM2 mapping: 8f x 4k per tile, o-split across (l ^ 16)
    const int w2 = s >> 5;
    const int l  = t & 31;
    const int oh = l >> 4;
    const int tileid = w2 * 16 + (l & 15);
    const int f0 = (tileid >> 3) * 8;
    const int kb = (tileid & 7) * 4;
    const int ob = oh * 16;
    float* Yg = dyn + jg * YG_PER_GROUP;
    const int barid = 1 + jg;

    float accF[8];
    #pragma unroll
    for (int q = 0; q < 8; q++) accF[q] = 0.0f;

    #pragma unroll 1
    for (int jb = 0; jb < 4; jb++) {
        const int j0 = jb * 8 + jg * 2;     // j1 = j0 + 1

        // ---- GEMM1 for both j (register reuse of As/Ps) ----
        u64 yA[4][2], yB[4][2];
        {
            float4 bA = *(const float4*)&BaseT[j0 * 32 + o0];
            float4 bB = *(const float4*)&BaseT[(j0 + 1) * 32 + o0];
            float aA[4] = { bA.x, bA.y, bA.z, bA.w };
            float aB[4] = { bB.x, bB.y, bB.z, bB.w };
            #pragma unroll
            for (int oi = 0; oi < 4; oi++) {
                float4 r = *(const float4*)&Rk_[(o0 + oi) * 32 + k0];
                yA[oi][0] = pk2(r.x + aA[oi], r.y + aA[oi]);
                yA[oi][1] = pk2(r.z + aA[oi], r.w + aA[oi]);
                yB[oi][0] = pk2(r.x + aB[oi], r.y + aB[oi]);
                yB[oi][1] = pk2(r.z + aB[oi], r.w + aB[oi]);
            }
        }
        #pragma unroll
        for (int d = 0; d < 32; d++) {
            float2 ajp = *(const float2*)&As_[d * 32 + j0];
            ulonglong2 a2 = *(const ulonglong2*)&As_[d * 32 + k0];
            u64 ajA = pk2(ajp.x, ajp.x);
            u64 ajB = pk2(ajp.y, ajp.y);
            u64 sA01 = mul2(a2.x, ajA), sA23 = mul2(a2.y, ajA);
            u64 sB01 = mul2(a2.x, ajB), sB23 = mul2(a2.y, ajB);
            float4 p4 = *(const float4*)&PsM[d * 32 + o0];
            u64 pd;
            pd = pk2(p4.x, p4.x);
            yA[0][0] = fma2(pd, sA01, yA[0][0]); yA[0][1] = fma2(pd, sA23, yA[0][1]);
            yB[0][0] = fma2(pd, sB01, yB[0][0]); yB[0][1] = fma2(pd, sB23, yB[0][1]);
            pd = pk2(p4.y, p4.y);
            yA[1][0] = fma2(pd, sA01, yA[1][0]); yA[1][1] = fma2(pd, sA23, yA[1][1]);
            yB[1][0] = fma2(pd, sB01, yB[1][0]); yB[1][1] = fma2(pd, sB23, yB[1][1]);
            pd = pk2(p4.z, p4.z);
            yA[2][0] = fma2(pd, sA01, yA[2][0]); yA[2][1] = fma2(pd, sA23, yA[2][1]);
            yB[2][0] = fma2(pd, sB01, yB[2][0]); yB[2][1] = fma2(pd, sB23, yB[2][1]);
            pd = pk2(p4.w, p4.w);
            yA[3][0] = fma2(pd, sA01, yA[3][0]); yA[3][1] = fma2(pd, sA23, yA[3][1]);
            yB[3][0] = fma2(pd, sB01, yB[3][0]); yB[3][1] = fma2(pd, sB23, yB[3][1]);
        }

        // ---- two halves: store tile -> bar -> GEMM2 -> bar ----
        #pragma unroll
        for (int half = 0; half < 2; half++) {
            u64 (*yy)[2] = half ? yB : yA;

            #pragma unroll
            for (int oi = 0; oi < 4; oi++) {
                float v0, v1, v2, v3;
                upk2(yy[oi][0], v0, v1); upk2(yy[oi][1], v2, v3);
                float4 v;
                v.x = fmaxf(v0, 0.f); v.y = fmaxf(v1, 0.f);
                v.z = fmaxf(v2, 0.f); v.w = fmaxf(v3, 0.f);
                *(float4*)&Yg[(o0 + oi) * YSTRIDE + k0] = v;
            }
            asm volatile("bar.sync %0, %1;" :: "r"(barid), "r"(64) : "memory");

            // GEMM2: z[f,k] partial over my o-half, then shfl-combine with lane^16
            u64 z[8][2];
            #pragma unroll
            for (int fi = 0; fi < 8; fi++) { z[fi][0] = 0ull; z[fi][1] = 0ull; }
            #pragma unroll
            for (int oo = 0; oo < 16; oo++) {
                const int o = ob + oo;
                float4 wa = *(const float4*)&Fwm[o * 32 + f0];
                float4 wb = *(const float4*)&Fwm[o * 32 + f0 + 4];
                ulonglong2 ya = *(const ulonglong2*)&Yg[o * YSTRIDE + kb];
                float wv[8] = { wa.x, wa.y, wa.z, wa.w, wb.x, wb.y, wb.z, wb.w };
                #pragma unroll
                for (int fi = 0; fi < 8; fi++) {
                    u64 wd = pk2(wv[fi], wv[fi]);
                    z[fi][0] = fma2(wd, ya.x, z[fi][0]);
                    z[fi][1] = fma2(wd, ya.y, z[fi][1]);
                }
            }
            #pragma unroll
            for (int fi = 0; fi < 8; fi++) {
                const float fb_ = fbv[f0 + fi];
                #pragma unroll
                for (int idx = 0; idx < 2; idx++) {
                    float a0, a1;
                    upk2(z[fi][idx], a0, a1);
                    a0 += __shfl_xor_sync(0xffffffffu, a0, 16);
                    a1 += __shfl_xor_sync(0xffffffffu, a1, 16);
                    if (idx == oh)
                        accF[fi] += fmaxf(a0 + fb_, 0.0f) + fmaxf(a1 + fb_, 0.0f);
                }
            }
            asm volatile("bar.sync %0, %1;" :: "r"(barid), "r"(64) : "memory");
        }
    }

    // ---- deterministic block reduction (Prt aliases dyn) ----
    __syncthreads();
    float* Prt = dyn;
    #pragma unroll
    for (int q = 0; q < 8; q += 4)
        *(float4*)&Prt[t * 8 + q] = make_float4(accF[q], accF[q+1], accF[q+2], accF[q+3]);
    __syncthreads();
    if (t < 32) {
        const int f = t;
        const int fg = f >> 3, fi = f & 7;
        float acc = 0.0f;
        #pragma unroll
        for (int g = 0; g < 4; g++)
            #pragma unroll
            for (int ohh = 0; ohh < 2; ohh++)
                #pragma unroll
                for (int r = 0; r < 8; r++)
                    acc += Prt[(g * 64 + (fg >> 1) * 32 + ohh * 16 + (fg & 1) * 8 + r) * 8 + fi];
        gPart[b][i][f] = acc;
    }
    __threadfence();
    __syncthreads();

    // ---- last block performs the final head ----
    if (t == 0) {
        unsigned int old = atomicAdd(&gCount, 1u);
        isLast = (old == (unsigned)(BATCH * NN - 1)) ? 1u : 0u;
    }
    __syncthreads();
    if (isLast) {
        __threadfence();
        const int bb = t >> 5, oo = t & 31;
        float acc = 0.0f;
        #pragma unroll
        for (int ii = 0; ii < NN; ii++) acc += gPart[bb][ii][oo];
        float v = fmaxf(acc, 0.0f) * out_w[oo];
        #pragma unroll
        for (int off = 16; off; off >>= 1) v += __shfl_down_sync(0xffffffffu, v, off);
        if (oo == 0) out[bb] = v + out_b[0];
        __syncthreads();
        if (t == 0) gCount = 0u;   // reset for next replay
    }
}

extern "C" void kernel_launch(void* const* d_in, const int* in_sizes, int n_in,
                              void* d_out, int out_size)
{
    const float* x    = (const float*)d_in[0];
    const float* W1   = (const float*)d_in[1];
    const float* b1   = (const float*)d_in[2];
    const float* W2   = (const float*)d_in[3];
    const float* b2   = (const float*)d_in[4];
    const float* eq   = (const float*)d_in[5];
    const float* eqb  = (const float*)d_in[6];
    const float* fcw  = (const float*)d_in[7];
    const float* fcb  = (const float*)d_in[8];
    const float* outw = (const float*)d_in[9];
    const float* outb = (const float*)d_in[10];
    float* out = (float*)d_out;

    fused_kernel<<<BATCH * NN, 256, DYN_FLOATS * sizeof(float)>>>(
        x, W1, b1, W2, b2, eq, eqb, fcw, fcb, outw, outb, out);
}